// round 14
// baseline (speedup 1.0000x reference)
#include <cuda_runtime.h>
#include <cuda_bf16.h>
#include <cstdint>

// 3D Haar DWT, x: (B=2, C=32, D=64, H=128, W=128) fp32
// out: low (2,32,32,64,64) then highs (2,32,7,32,64,64), packed.
//
// FINAL: dynamic store-rotation variant — the only configuration measured
// below 82us (80.51, 81.70 vs static cluster 81.95-82.18 across 5 runs).
// Mechanism: dynamic o[] indexing raises regs to 78 (occ ~30%, fewer
// concurrent warps -> less cross-CTA L1tex-queue contention) and spreads
// store issue in time, smoothing DRAM write pressure. Traffic is minimal
// (512MB); DRAM ~81% is the B300 mixed-R/W controller ceiling.

#define C_HAAR 0.35355339059327373f  // 1/(2*sqrt(2))

__global__ __launch_bounds__(256) void dwt3d_haar_kernel(
    const float* __restrict__ x, float* __restrict__ out)
{
    // total threads = 2,097,152 = 64(bc) * 32(d) * 64(h) * 16(wg)
    unsigned tid = blockIdx.x * 256u + threadIdx.x;
    unsigned wg = tid & 15u;          // w-group: 4 output w per group
    unsigned h  = (tid >> 4) & 63u;   // output h (0..63)
    unsigned d  = (tid >> 10) & 31u;  // output d (0..31)
    unsigned bc = tid >> 15;          // b*C + c (0..63)

    // input: ((bc)*64 + 2d+i)*16384 + (2h+j)*128 + 8*wg
    size_t in_base = ((size_t)bc << 20)
                   + ((size_t)d << 15)
                   + ((size_t)h << 8)
                   + (wg << 3);

    // Load 4 rows (i,j in {0,1}^2), 8 contiguous floats each (2x LDG.128),
    // streaming (evict-first) — no reuse anywhere.
    float4 r[4][2];
#pragma unroll
    for (int i = 0; i < 2; i++) {
#pragma unroll
        for (int j = 0; j < 2; j++) {
            const float4* p = reinterpret_cast<const float4*>(
                x + in_base + (size_t)i * 16384 + (size_t)j * 128);
            r[i * 2 + j][0] = __ldcs(p);
            r[i * 2 + j][1] = __ldcs(p + 1);
        }
    }

    // o[s][m]: subband s (i*4 + j*2 + k bits, 0=low-pass), output site m (0..3)
    float o[8][4];

#pragma unroll
    for (int m = 0; m < 4; m++) {
        float ka[2][2], kb[2][2];  // k-stage sum/diff
#pragma unroll
        for (int i = 0; i < 2; i++) {
#pragma unroll
            for (int j = 0; j < 2; j++) {
                float4 q = r[i * 2 + j][m >> 1];
                float v0 = (m & 1) ? q.z : q.x;
                float v1 = (m & 1) ? q.w : q.y;
                ka[i][j] = v0 + v1;
                kb[i][j] = v0 - v1;
            }
        }
        float t[2][2][2];  // t[x][y][i]: after j-stage
#pragma unroll
        for (int i = 0; i < 2; i++) {
            t[0][0][i] = ka[i][0] + ka[i][1];
            t[0][1][i] = ka[i][0] - ka[i][1];
            t[1][0][i] = kb[i][0] + kb[i][1];
            t[1][1][i] = kb[i][0] - kb[i][1];
        }
#pragma unroll
        for (int y = 0; y < 2; y++) {
#pragma unroll
            for (int xk = 0; xk < 2; xk++) {
                o[0 * 4 + y * 2 + xk][m] = C_HAAR * (t[xk][y][0] + t[xk][y][1]);
                o[1 * 4 + y * 2 + xk][m] = C_HAAR * (t[xk][y][0] - t[xk][y][1]);
            }
        }
    }

    // Output addresses: spatial = d*4096 + h*64 + 4*wg
    unsigned spatial = (d << 12) + (h << 6) + (wg << 2);

    // Store all 8 subbands, starting at a warp-dependent rotation so the 8
    // write streams are concurrently active chip-wide.
    unsigned rot = (tid >> 5) & 7u;  // warp id mod 8
#pragma unroll
    for (int q = 0; q < 8; q++) {
        unsigned s = (q + rot) & 7u;
        float4 v = make_float4(o[s][0], o[s][1], o[s][2], o[s][3]);
        size_t off;
        if (s == 0) {
            off = ((size_t)bc << 17) + spatial;                              // low
        } else {
            off = 8388608u + ((size_t)(bc * 7u + (s - 1)) << 17) + spatial;  // highs
        }
        __stcs(reinterpret_cast<float4*>(out + off), v);
    }
}

extern "C" void kernel_launch(void* const* d_in, const int* in_sizes, int n_in,
                              void* d_out, int out_size)
{
    const float* x = (const float*)d_in[0];
    float* out = (float*)d_out;
    dwt3d_haar_kernel<<<8192, 256>>>(x, out);
}

// round 15
// speedup vs baseline: 1.0063x; 1.0063x over previous
#include <cuda_runtime.h>
#include <cuda_bf16.h>
#include <cstdint>

// 3D Haar DWT, x: (B=2, C=32, D=64, H=128, W=128) fp32
// out: low (2,32,32,64,64) then highs (2,32,7,32,64,64), packed.
//
// R15: occupancy-cap probe. Champion structure (static store order, regs 44,
// clean SASS) + 48KB unused smem -> 4 CTAs/SM. Tests whether the dynamic-
// rotation variant's occasional sub-81us runs came from reduced cross-CTA
// L1tex-queue contention at lower occupancy, isolated from its ALU tax.

#define C_HAAR 0.35355339059327373f  // 1/(2*sqrt(2))

__global__ __launch_bounds__(256) void dwt3d_haar_kernel(
    const float* __restrict__ x, float* __restrict__ out)
{
    // Occupancy limiter: 48KB smem -> 4 CTAs/SM. Touched once so it can't
    // be elided; never read.
    __shared__ volatile char occ_pad[49152];
    occ_pad[threadIdx.x] = (char)threadIdx.x;

    // total threads = 2,097,152 = 64(bc) * 32(d) * 64(h) * 16(wg)
    unsigned tid = blockIdx.x * 256u + threadIdx.x;
    unsigned wg = tid & 15u;          // w-group: 4 output w per group
    unsigned h  = (tid >> 4) & 63u;   // output h (0..63)
    unsigned d  = (tid >> 10) & 31u;  // output d (0..31)
    unsigned bc = tid >> 15;          // b*C + c (0..63)

    // input: ((bc)*64 + 2d+i)*16384 + (2h+j)*128 + 8*wg
    size_t in_base = ((size_t)bc << 20)
                   + ((size_t)d << 15)
                   + ((size_t)h << 8)
                   + (wg << 3);

    // Load 4 rows (i,j in {0,1}^2), 8 contiguous floats each (2x LDG.128),
    // streaming (evict-first) — no reuse anywhere.
    float4 r[4][2];
#pragma unroll
    for (int i = 0; i < 2; i++) {
#pragma unroll
        for (int j = 0; j < 2; j++) {
            const float4* p = reinterpret_cast<const float4*>(
                x + in_base + (size_t)i * 16384 + (size_t)j * 128);
            r[i * 2 + j][0] = __ldcs(p);
            r[i * 2 + j][1] = __ldcs(p + 1);
        }
    }

    // o[s][m]: subband s (i*4 + j*2 + k bits, 0=low-pass), output site m (0..3)
    float o[8][4];

#pragma unroll
    for (int m = 0; m < 4; m++) {
        float ka[2][2], kb[2][2];  // k-stage sum/diff
#pragma unroll
        for (int i = 0; i < 2; i++) {
#pragma unroll
            for (int j = 0; j < 2; j++) {
                float4 q = r[i * 2 + j][m >> 1];
                float v0 = (m & 1) ? q.z : q.x;
                float v1 = (m & 1) ? q.w : q.y;
                ka[i][j] = v0 + v1;
                kb[i][j] = v0 - v1;
            }
        }
        float t[2][2][2];  // t[x][y][i]: after j-stage
#pragma unroll
        for (int i = 0; i < 2; i++) {
            t[0][0][i] = ka[i][0] + ka[i][1];
            t[0][1][i] = ka[i][0] - ka[i][1];
            t[1][0][i] = kb[i][0] + kb[i][1];
            t[1][1][i] = kb[i][0] - kb[i][1];
        }
#pragma unroll
        for (int y = 0; y < 2; y++) {
#pragma unroll
            for (int xk = 0; xk < 2; xk++) {
                o[0 * 4 + y * 2 + xk][m] = C_HAAR * (t[xk][y][0] + t[xk][y][1]);
                o[1 * 4 + y * 2 + xk][m] = C_HAAR * (t[xk][y][0] - t[xk][y][1]);
            }
        }
    }

    // Output addresses: spatial = d*4096 + h*64 + 4*wg
    unsigned spatial = (d << 12) + (h << 6) + (wg << 2);

    // low: out[bc*131072 + spatial]
    {
        float4 v = make_float4(o[0][0], o[0][1], o[0][2], o[0][3]);
        __stcs(reinterpret_cast<float4*>(out + ((size_t)bc << 17) + spatial), v);
    }
    // highs: out[8388608 + (bc*7 + (s-1))*131072 + spatial]
#pragma unroll
    for (int s = 1; s < 8; s++) {
        float4 v = make_float4(o[s][0], o[s][1], o[s][2], o[s][3]);
        size_t off = 8388608u + ((size_t)(bc * 7u + (unsigned)(s - 1)) << 17) + spatial;
        __stcs(reinterpret_cast<float4*>(out + off), v);
    }
}

extern "C" void kernel_launch(void* const* d_in, const int* in_sizes, int n_in,
                              void* d_out, int out_size)
{
    const float* x = (const float*)d_in[0];
    float* out = (float*)d_out;
    dwt3d_haar_kernel<<<8192, 256>>>(x, out);
}

// round 16
// speedup vs baseline: 1.0199x; 1.0135x over previous
#include <cuda_runtime.h>
#include <cuda_bf16.h>
#include <cstdint>

// 3D Haar DWT, x: (B=2, C=32, D=64, H=128, W=128) fp32
// out: low (2,32,32,64,64) then highs (2,32,7,32,64,64), packed.
//
// R16: occupancy gradient step. Static-store champion + 64KB smem pad ->
// 3 CTAs/SM (24 warps). Measured trend: occ 47% -> 82.1us, 38% -> 81.5us,
// ~29% (dynamic variant) -> 81.4us mean. Mechanism: fewer resident CTAs cut
// cross-CTA L1tex-queue contention (MLP_p1=8 front-batched LDGs).

#define C_HAAR 0.35355339059327373f  // 1/(2*sqrt(2))

__global__ __launch_bounds__(256) void dwt3d_haar_kernel(
    const float* __restrict__ x, float* __restrict__ out)
{
    // Occupancy limiter: 64KB smem -> 3 CTAs/SM. Touched once; never read.
    __shared__ volatile char occ_pad[65536];
    occ_pad[threadIdx.x] = (char)threadIdx.x;

    // total threads = 2,097,152 = 64(bc) * 32(d) * 64(h) * 16(wg)
    unsigned tid = blockIdx.x * 256u + threadIdx.x;
    unsigned wg = tid & 15u;          // w-group: 4 output w per group
    unsigned h  = (tid >> 4) & 63u;   // output h (0..63)
    unsigned d  = (tid >> 10) & 31u;  // output d (0..31)
    unsigned bc = tid >> 15;          // b*C + c (0..63)

    // input: ((bc)*64 + 2d+i)*16384 + (2h+j)*128 + 8*wg
    size_t in_base = ((size_t)bc << 20)
                   + ((size_t)d << 15)
                   + ((size_t)h << 8)
                   + (wg << 3);

    // Load 4 rows (i,j in {0,1}^2), 8 contiguous floats each (2x LDG.128),
    // streaming (evict-first) — no reuse anywhere.
    float4 r[4][2];
#pragma unroll
    for (int i = 0; i < 2; i++) {
#pragma unroll
        for (int j = 0; j < 2; j++) {
            const float4* p = reinterpret_cast<const float4*>(
                x + in_base + (size_t)i * 16384 + (size_t)j * 128);
            r[i * 2 + j][0] = __ldcs(p);
            r[i * 2 + j][1] = __ldcs(p + 1);
        }
    }

    // o[s][m]: subband s (i*4 + j*2 + k bits, 0=low-pass), output site m (0..3)
    float o[8][4];

#pragma unroll
    for (int m = 0; m < 4; m++) {
        float ka[2][2], kb[2][2];  // k-stage sum/diff
#pragma unroll
        for (int i = 0; i < 2; i++) {
#pragma unroll
            for (int j = 0; j < 2; j++) {
                float4 q = r[i * 2 + j][m >> 1];
                float v0 = (m & 1) ? q.z : q.x;
                float v1 = (m & 1) ? q.w : q.y;
                ka[i][j] = v0 + v1;
                kb[i][j] = v0 - v1;
            }
        }
        float t[2][2][2];  // t[x][y][i]: after j-stage
#pragma unroll
        for (int i = 0; i < 2; i++) {
            t[0][0][i] = ka[i][0] + ka[i][1];
            t[0][1][i] = ka[i][0] - ka[i][1];
            t[1][0][i] = kb[i][0] + kb[i][1];
            t[1][1][i] = kb[i][0] - kb[i][1];
        }
#pragma unroll
        for (int y = 0; y < 2; y++) {
#pragma unroll
            for (int xk = 0; xk < 2; xk++) {
                o[0 * 4 + y * 2 + xk][m] = C_HAAR * (t[xk][y][0] + t[xk][y][1]);
                o[1 * 4 + y * 2 + xk][m] = C_HAAR * (t[xk][y][0] - t[xk][y][1]);
            }
        }
    }

    // Output addresses: spatial = d*4096 + h*64 + 4*wg
    unsigned spatial = (d << 12) + (h << 6) + (wg << 2);

    // low: out[bc*131072 + spatial]
    {
        float4 v = make_float4(o[0][0], o[0][1], o[0][2], o[0][3]);
        __stcs(reinterpret_cast<float4*>(out + ((size_t)bc << 17) + spatial), v);
    }
    // highs: out[8388608 + (bc*7 + (s-1))*131072 + spatial]
#pragma unroll
    for (int s = 1; s < 8; s++) {
        float4 v = make_float4(o[s][0], o[s][1], o[s][2], o[s][3]);
        size_t off = 8388608u + ((size_t)(bc * 7u + (unsigned)(s - 1)) << 17) + spatial;
        __stcs(reinterpret_cast<float4*>(out + off), v);
    }
}

extern "C" void kernel_launch(void* const* d_in, const int* in_sizes, int n_in,
                              void* d_out, int out_size)
{
    const float* x = (const float*)d_in[0];
    float* out = (float*)d_out;
    dwt3d_haar_kernel<<<8192, 256>>>(x, out);
}